// round 7
// baseline (speedup 1.0000x reference)
#include <cuda_runtime.h>
#include <cstdint>

#define E_TOT    131072
#define DDIM     128
#define KTOT     2048
#define TILE_E   128
#define NTHREADS 160          // 128 consumer + 32 producer
#define NCHUNKS  64
#define FSTRIDE  40           // floats per F row (32 + 8 pad): LDS conflict-free
#define FBUF_B   20480        // bytes per F buffer (128*40*4)

// ---- SMEM byte offsets ----
#define F0_OFF   0            // 4 F buffers, depth-4 ring
#define S3_OFF   81920        // 128 f
#define Q3_OFF   82432        // 128 f
#define CA_OFF   82944        // 16 f
#define CB_OFF   83008
#define CD_OFF   83072
#define ROW_OFF  83136        // 128 i
#define COL_OFF  83648
#define TYP_OFF  84160
#define DS_OFF   84672        // dsum 256 f
#define MB_OFF   85696        // full0-3 @ +0..24, empty0-3 @ +32..56
#define SMEM_BYTES 85760

// B in fragment-major order: [chunk][ks8][nblk][lane] as float2
// lane = gid*4+tig; value = (B[k'=chunk*32+ks8*8+tig][n], B[k'+4][n]), n = nblk*8+gid
__device__ float2 g_Bf[NCHUNKS * 4 * 16 * 32];

__device__ __forceinline__ uint32_t smem_u32(const void* p) {
    uint32_t a;
    asm("{ .reg .u64 t; cvta.to.shared.u64 t, %1; cvt.u32.u64 %0, t; }"
        : "=r"(a) : "l"(p));
    return a;
}
__device__ __forceinline__ float tf32r(float x) {
    uint32_t r;
    asm("cvt.rna.tf32.f32 %0, %1;" : "=r"(r) : "f"(x));
    return __uint_as_float(r);
}
__device__ __forceinline__ void mma_tf32(float* c, const uint32_t* a,
                                         uint32_t b0, uint32_t b1) {
    asm volatile(
        "mma.sync.aligned.m16n8k8.row.col.f32.tf32.tf32.f32 "
        "{%0,%1,%2,%3}, {%4,%5,%6,%7}, {%8,%9}, {%0,%1,%2,%3};"
        : "+f"(c[0]), "+f"(c[1]), "+f"(c[2]), "+f"(c[3])
        : "r"(a[0]), "r"(a[1]), "r"(a[2]), "r"(a[3]), "r"(b0), "r"(b1));
}
__device__ __forceinline__ void mbar_init(uint32_t mb, uint32_t cnt) {
    asm volatile("mbarrier.init.shared.b64 [%0], %1;" :: "r"(mb), "r"(cnt) : "memory");
}
__device__ __forceinline__ void mbar_arrive(uint32_t mb) {
    asm volatile("mbarrier.arrive.shared.b64 _, [%0];" :: "r"(mb) : "memory");
}
__device__ __forceinline__ void mbar_wait(uint32_t mb, uint32_t parity) {
    asm volatile(
        "{\n\t"
        ".reg .pred P;\n\t"
        "LAB_W%=:\n\t"
        "mbarrier.try_wait.parity.acquire.cta.shared::cta.b64 P, [%0], %1, 0x989680;\n\t"
        "@P bra.uni LAB_D%=;\n\t"
        "bra.uni LAB_W%=;\n\t"
        "LAB_D%=:\n\t"
        "}"
        :: "r"(mb), "r"(parity) : "memory");
}

// ===== prep: build fragment-major, tf32-rounded B from fc_w =====
// logical k' = j*16 + c  (j-major over channels);  klog = c*128 + j
extern "C" __global__ void conve_prep(const float* __restrict__ fc_w)
{
    const int idx = blockIdx.x * 256 + threadIdx.x;   // 0 .. 131071
    const int lane  = idx & 31;
    const int nblk  = (idx >> 5) & 15;
    const int ks8   = (idx >> 9) & 3;
    const int chunk = idx >> 11;
    const int gid = lane >> 2;
    const int tig = lane & 3;
    const int n = nblk * 8 + gid;

    const int kp0 = chunk * 32 + ks8 * 8 + tig;
    const int kp1 = kp0 + 4;
    const int klog0 = (kp0 & 15) * 128 + (kp0 >> 4);
    const int klog1 = (kp1 & 15) * 128 + (kp1 >> 4);
    float2 v;
    v.x = tf32r(fc_w[(long)klog0 * DDIM + n]);
    v.y = tf32r(fc_w[(long)klog1 * DDIM + n]);
    g_Bf[idx] = v;
}

// ===== main: 2 CTAs/SM, 4 fat consumer warps (4m x 8n) + 1 producer warp =====
extern "C" __global__ void __launch_bounds__(NTHREADS, 2)
conve_main(const float* __restrict__ h, const float* __restrict__ g,
           const int* __restrict__ eidx, const int* __restrict__ etype,
           const float* __restrict__ conv_w, const float* __restrict__ conv_b,
           const float* __restrict__ fc_b,
           const float* __restrict__ bn1g, const float* __restrict__ bn1b,
           const float* __restrict__ bn1m, const float* __restrict__ bn1v,
           const float* __restrict__ bn3g, const float* __restrict__ bn3b,
           const float* __restrict__ bn3m, const float* __restrict__ bn3v,
           float* __restrict__ out)
{
    extern __shared__ char smc[];
    float* S3 = (float*)(smc + S3_OFF);
    float* Q3 = (float*)(smc + Q3_OFF);
    float* CA = (float*)(smc + CA_OFF);
    float* CB = (float*)(smc + CB_OFF);
    float* CD = (float*)(smc + CD_OFF);
    int* ROW = (int*)(smc + ROW_OFF);
    int* COL = (int*)(smc + COL_OFF);
    int* TYP = (int*)(smc + TYP_OFF);

    const uint32_t smem_base = smem_u32(smc);
    const int tid = threadIdx.x;
    const int e0  = blockIdx.x * TILE_E;

    if (tid == 0) {
#pragma unroll
        for (int i = 0; i < 4; i++) {
            mbar_init(smem_base + MB_OFF + i * 8, 32);        // full: producer warp
            mbar_init(smem_base + MB_OFF + 32 + i * 8, 128);  // empty: consumers
        }
    }
    if (tid < DDIM) {
        float s = bn3g[tid] * rsqrtf(bn3v[tid] + 1e-5f);
        S3[tid] = s;
        Q3[tid] = fc_b[tid] * s + bn3b[tid] - bn3m[tid] * s;
        ROW[tid] = eidx[e0 + tid];
        COL[tid] = eidx[E_TOT + e0 + tid];
        TYP[tid] = etype[e0 + tid];
    }
    if (tid < 16) {
        float s1 = bn1g[0] * rsqrtf(bn1v[0] + 1e-5f);
        float b1 = bn1b[0] - bn1m[0] * s1;
        float w0 = conv_w[tid * 2], w1 = conv_w[tid * 2 + 1];
        CA[tid] = w0 * s1;
        CB[tid] = w1 * s1;
        CD[tid] = (w0 + w1) * b1 + conv_b[tid];
    }
    __syncthreads();

    if (tid >= 128) {
        // ================= PRODUCER (warp 4, 32 threads) =================
        const int ptid = tid - 128;
        const int pseg = ptid & 7;        // 16B k segment
        const int rgrp = ptid >> 3;       // 0..3 -> rows rgrp*32 .. +31

        // stored-index -> (channel coeffs, j-select), chunk-invariant
        float caq[4], cbq[4], cdq[4];
        int   jsel[4];
#pragma unroll
        for (int q = 0; q < 4; q++) {
            const int st = pseg * 4 + q;
            const int kl = (st & ~7) | ((st >> 1) & 3) | ((st & 1) << 2);
            const int c  = kl & 15;
            jsel[q] = kl >> 4;
            caq[q] = CA[c]; cbq[q] = CB[c]; cdq[q] = CD[c];
        }

        for (int chunk = 0; chunk < NCHUNKS; chunk++) {
            const int buf = chunk & 3;
            const int j0  = chunk * 2;
            mbar_wait(smem_base + MB_OFF + 32 + buf * 8, ((chunk >> 2) & 1) ^ 1);
            float* F = (float*)(smc + F0_OFF + buf * FBUF_B);
#pragma unroll 4
            for (int p = 0; p < 32; p++) {
                const int r = rgrp * 32 + p;
                const float2 u = __ldg((const float2*)(h + (long)ROW[r] * DDIM + j0));
                const float2 v = __ldg((const float2*)(g + (long)TYP[r] * DDIM + j0));
                float fr[4];
#pragma unroll
                for (int q = 0; q < 4; q++) {
                    const float uu = jsel[q] ? u.y : u.x;
                    const float vv = jsel[q] ? v.y : v.x;
                    float f = fmaf(caq[q], uu, fmaf(cbq[q], vv, cdq[q]));
                    fr[q] = tf32r(fmaxf(f, 0.0f));
                }
                *(float4*)&F[r * FSTRIDE + pseg * 4] =
                    make_float4(fr[0], fr[1], fr[2], fr[3]);
            }
            mbar_arrive(smem_base + MB_OFF + buf * 8);
        }
    } else {
        // ================= CONSUMER (warps 0-3, 64m x 64n each) =================
        const int wid  = tid >> 5;
        const int lane = tid & 31;
        const int gid  = lane >> 2;
        const int tig  = lane & 3;
        const int ebase = (wid & 1) * 64;
        const int nblk0 = (wid >> 1) * 8;     // n block base (8 n8-blocks)

        float acc[4][8][4];
#pragma unroll
        for (int mt = 0; mt < 4; mt++)
#pragma unroll
            for (int nt = 0; nt < 8; nt++)
#pragma unroll
                for (int q = 0; q < 4; q++) acc[mt][nt][q] = 0.0f;

        for (int chunk = 0; chunk < NCHUNKS; chunk++) {
            const int buf = chunk & 3;
            mbar_wait(smem_base + MB_OFF + buf * 8, (chunk >> 2) & 1);
            const float* F = (const float*)(smc + F0_OFF + buf * FBUF_B);
#pragma unroll
            for (int ks8 = 0; ks8 < 4; ks8++) {
                // B fragments straight from L2/L1 (coalesced 256B per warp-load)
                const float2* bp = g_Bf + (((long)(chunk * 4 + ks8) * 16) << 5) + lane;
                float2 bf[8];
#pragma unroll
                for (int nt = 0; nt < 8; nt++)
                    bf[nt] = __ldg(bp + ((nblk0 + nt) << 5));
                // A fragments from SMEM
                uint32_t a[4][4];
                const int ko = ks8 * 8 + 2 * tig;
#pragma unroll
                for (int mt = 0; mt < 4; mt++) {
                    const int r = ebase + mt * 16 + gid;
                    const float2 fa = *(const float2*)&F[r * FSTRIDE + ko];
                    const float2 fb = *(const float2*)&F[(r + 8) * FSTRIDE + ko];
                    a[mt][0] = __float_as_uint(fa.x);
                    a[mt][1] = __float_as_uint(fb.x);
                    a[mt][2] = __float_as_uint(fa.y);
                    a[mt][3] = __float_as_uint(fb.y);
                }
#pragma unroll
                for (int nt = 0; nt < 8; nt++) {
                    const uint32_t b0 = __float_as_uint(bf[nt].x);
                    const uint32_t b1 = __float_as_uint(bf[nt].y);
#pragma unroll
                    for (int mt = 0; mt < 4; mt++)
                        mma_tf32(acc[mt][nt], a[mt], b0, b1);
                }
            }
            mbar_arrive(smem_base + MB_OFF + 32 + buf * 8);
        }

        // ---- epilogue: bn3 + relu + dot(h[col]) over this warp's 64-col slice ----
        const int nwarp = (wid >> 1);     // 0 or 1 (n half)
        float dotp[8];
        long cb8[8];
#pragma unroll
        for (int rr = 0; rr < 8; rr++) {
            dotp[rr] = 0.0f;
            const int e = ebase + (rr >> 1) * 16 + (rr & 1) * 8 + gid;
            cb8[rr] = (long)COL[e] * DDIM;
        }
#pragma unroll
        for (int nt = 0; nt < 8; nt++) {
            const int n = nwarp * 64 + nt * 8 + 2 * tig;
            const float2 s3 = *(const float2*)&S3[n];
            const float2 q3 = *(const float2*)&Q3[n];
#pragma unroll
            for (int mt = 0; mt < 4; mt++) {
#pragma unroll
                for (int hh = 0; hh < 2; hh++) {
                    const int rr = mt * 2 + hh;
                    float z0 = fmaxf(fmaf(acc[mt][nt][hh * 2 + 0], s3.x, q3.x), 0.0f);
                    float z1 = fmaxf(fmaf(acc[mt][nt][hh * 2 + 1], s3.y, q3.y), 0.0f);
                    const float2 c2 = __ldg((const float2*)(h + cb8[rr] + n));
                    dotp[rr] = fmaf(z0, c2.x, fmaf(z1, c2.y, dotp[rr]));
                }
            }
        }
        float* dsum = (float*)(smc + DS_OFF);
#pragma unroll
        for (int rr = 0; rr < 8; rr++) {
            float s = dotp[rr];
            s += __shfl_xor_sync(0xffffffffu, s, 1, 4);
            s += __shfl_xor_sync(0xffffffffu, s, 2, 4);
            if (tig == 0) {
                const int e = ebase + (rr >> 1) * 16 + (rr & 1) * 8 + gid;
                dsum[nwarp * TILE_E + e] = s;
            }
        }
    }

    __syncthreads();   // join producer + consumers; dsum visible
    if (tid < TILE_E) {
        const float* ds = (const float*)(smc + DS_OFF);
        out[e0 + tid] = ds[tid] + ds[TILE_E + tid];
    }
}

// ===== launch =====
extern "C" void kernel_launch(void* const* d_in, const int* in_sizes, int n_in,
                              void* d_out, int out_size)
{
    const float* h      = (const float*)d_in[0];
    const float* g      = (const float*)d_in[1];
    const int*   eidx   = (const int*)d_in[2];
    const int*   etype  = (const int*)d_in[3];
    const float* conv_w = (const float*)d_in[4];
    const float* conv_b = (const float*)d_in[5];
    const float* fc_w   = (const float*)d_in[6];
    const float* fc_b   = (const float*)d_in[7];
    const float* bn1g   = (const float*)d_in[8];
    const float* bn1b   = (const float*)d_in[9];
    const float* bn1m   = (const float*)d_in[10];
    const float* bn1v   = (const float*)d_in[11];
    const float* bn3g   = (const float*)d_in[12];
    const float* bn3b   = (const float*)d_in[13];
    const float* bn3m   = (const float*)d_in[14];
    const float* bn3v   = (const float*)d_in[15];
    float* out = (float*)d_out;

    conve_prep<<<512, 256>>>(fc_w);   // 131072 fragment pairs

    cudaFuncSetAttribute(conve_main,
                         cudaFuncAttributeMaxDynamicSharedMemorySize, SMEM_BYTES);
    conve_main<<<E_TOT / TILE_E, NTHREADS, SMEM_BYTES>>>(
        h, g, eidx, etype, conv_w, conv_b, fc_b,
        bn1g, bn1b, bn1m, bn1v, bn3g, bn3b, bn3m, bn3v, out);
}

// round 8
// speedup vs baseline: 6.2826x; 6.2826x over previous
#include <cuda_runtime.h>
#include <cuda_fp16.h>
#include <cstdint>

#define E_TOT    131072
#define DDIM     128
#define KTOT     2048
#define TILE_E   64
#define NTHREADS 320          // 256 consumer + 64 producer
#define NCHUNKS  64

// ---- SMEM layout per CTA ----
// 4-stage ring; each stage: F frag-major 4KB  +  B frag-major 8KB
#define STAGE_B   12288
#define F_IN_STG  0
#define B_IN_STG  4096
#define RING_B    (4 * STAGE_B)          // 49152
#define S3_OFF    49152                  // 128 f
#define Q3_OFF    49664                  // 128 f
#define CA_OFF    50176                  // 16 f
#define CB_OFF    50240
#define CD_OFF    50304
#define ROW_OFF   50368                  // 64 i
#define COL_OFF   50624
#define TYP_OFF   50880
#define DS_OFF    51136                  // 4*64 f = 1024B
#define MB_OFF    52160                  // full0-3, empty0-3
#define SMEM_BYTES 52224

// fc_w in fp16, fragment-major: [chunk][s][nblk][lane] * 4 halves
// lane = gid*4+tig; halves = {B[k=2tig][n], B[2tig+1][n], B[8+2tig][n], B[9+2tig][n]}
// n = nblk*8+gid;  k relative to (chunk,s): k' = chunk*32+s*16+kk, j=chunk*2+s, c=kk
__device__ __half g_Bh[NCHUNKS * 2 * 16 * 32 * 4];

__device__ __forceinline__ uint32_t smem_u32(const void* p) {
    uint32_t a;
    asm("{ .reg .u64 t; cvta.to.shared.u64 t, %1; cvt.u32.u64 %0, t; }"
        : "=r"(a) : "l"(p));
    return a;
}
__device__ __forceinline__ void mma_f16(float* c, uint32_t a0, uint32_t a1,
                                        uint32_t a2, uint32_t a3,
                                        uint32_t b0, uint32_t b1) {
    asm volatile(
        "mma.sync.aligned.m16n8k16.row.col.f32.f16.f16.f32 "
        "{%0,%1,%2,%3}, {%4,%5,%6,%7}, {%8,%9}, {%0,%1,%2,%3};"
        : "+f"(c[0]), "+f"(c[1]), "+f"(c[2]), "+f"(c[3])
        : "r"(a0), "r"(a1), "r"(a2), "r"(a3), "r"(b0), "r"(b1));
}
__device__ __forceinline__ void mbar_init(uint32_t mb, uint32_t cnt) {
    asm volatile("mbarrier.init.shared.b64 [%0], %1;" :: "r"(mb), "r"(cnt) : "memory");
}
__device__ __forceinline__ void mbar_arrive(uint32_t mb) {
    asm volatile("mbarrier.arrive.shared.b64 _, [%0];" :: "r"(mb) : "memory");
}
__device__ __forceinline__ void mbar_wait(uint32_t mb, uint32_t parity) {
    asm volatile(
        "{\n\t"
        ".reg .pred P;\n\t"
        "LAB_W%=:\n\t"
        "mbarrier.try_wait.parity.acquire.cta.shared::cta.b64 P, [%0], %1, 0x989680;\n\t"
        "@P bra.uni LAB_D%=;\n\t"
        "bra.uni LAB_W%=;\n\t"
        "LAB_D%=:\n\t"
        "}"
        :: "r"(mb), "r"(parity) : "memory");
}

// ===== prep: fragment-major fp16 B from fc_w =====
extern "C" __global__ void conve_prep(const float* __restrict__ fc_w)
{
    const int idx = blockIdx.x * 256 + threadIdx.x;     // 0..65535 (8B units)
    const int lane  = idx & 31;
    const int nblk  = (idx >> 5) & 15;
    const int s     = (idx >> 9) & 1;
    const int chunk = idx >> 10;
    const int gid = lane >> 2;
    const int tig = lane & 3;
    const int n = nblk * 8 + gid;
    const int j = chunk * 2 + s;

    const int c0 = 2 * tig, c1 = 2 * tig + 1, c2 = 8 + 2 * tig, c3 = 9 + 2 * tig;
    float f0 = fc_w[(long)(c0 * 128 + j) * DDIM + n];
    float f1 = fc_w[(long)(c1 * 128 + j) * DDIM + n];
    float f2 = fc_w[(long)(c2 * 128 + j) * DDIM + n];
    float f3 = fc_w[(long)(c3 * 128 + j) * DDIM + n];
    __half2* dst = (__half2*)(g_Bh + (long)idx * 4);
    dst[0] = __floats2half2_rn(f0, f1);
    dst[1] = __floats2half2_rn(f2, f3);
}

// ===== main: 2 CTAs/SM, 8 consumer warps (2m x 4n, fp16 k16) + 2 producer =====
extern "C" __global__ void __launch_bounds__(NTHREADS, 2)
conve_main(const float* __restrict__ h, const float* __restrict__ g,
           const int* __restrict__ eidx, const int* __restrict__ etype,
           const float* __restrict__ conv_w, const float* __restrict__ conv_b,
           const float* __restrict__ fc_b,
           const float* __restrict__ bn1g, const float* __restrict__ bn1b,
           const float* __restrict__ bn1m, const float* __restrict__ bn1v,
           const float* __restrict__ bn3g, const float* __restrict__ bn3b,
           const float* __restrict__ bn3m, const float* __restrict__ bn3v,
           float* __restrict__ out)
{
    extern __shared__ char smc[];
    float* S3 = (float*)(smc + S3_OFF);
    float* Q3 = (float*)(smc + Q3_OFF);
    float* CA = (float*)(smc + CA_OFF);
    float* CB = (float*)(smc + CB_OFF);
    float* CD = (float*)(smc + CD_OFF);
    int* ROW = (int*)(smc + ROW_OFF);
    int* COL = (int*)(smc + COL_OFF);
    int* TYP = (int*)(smc + TYP_OFF);

    const uint32_t smem_base = smem_u32(smc);
    const int tid = threadIdx.x;
    const int e0  = blockIdx.x * TILE_E;

    if (tid == 0) {
#pragma unroll
        for (int i = 0; i < 4; i++) {
            mbar_init(smem_base + MB_OFF + i * 8, 64);        // full: 64 producer thr
            mbar_init(smem_base + MB_OFF + 32 + i * 8, 256);  // empty: 256 consumer thr
        }
    }
    if (tid < DDIM) {
        float s = bn3g[tid] * rsqrtf(bn3v[tid] + 1e-5f);
        S3[tid] = s;
        Q3[tid] = fc_b[tid] * s + bn3b[tid] - bn3m[tid] * s;
    }
    if (tid < TILE_E) {
        ROW[tid] = eidx[e0 + tid];
        COL[tid] = eidx[E_TOT + e0 + tid];
        TYP[tid] = etype[e0 + tid];
    }
    if (tid < 16) {
        float s1 = bn1g[0] * rsqrtf(bn1v[0] + 1e-5f);
        float b1 = bn1b[0] - bn1m[0] * s1;
        float w0 = conv_w[tid * 2], w1 = conv_w[tid * 2 + 1];
        CA[tid] = w0 * s1;
        CB[tid] = w1 * s1;
        CD[tid] = (w0 + w1) * b1 + conv_b[tid];
    }
    __syncthreads();

    if (tid >= 256) {
        // ================= PRODUCER (warps 8-9) =================
        const int ptid = tid - 256;            // 0..63
        const int gid  = (ptid >> 2) & 7;
        const int tig  = ptid & 3;
        const int rb2  = ptid >> 5;            // 0/1 -> handles rb2, rb2+2

        // 4 channels for this tig
        float ca4[4], cb4[4], cd4[4];
#pragma unroll
        for (int q = 0; q < 4; q++) {
            const int c = (q < 2) ? (2 * tig + q) : (8 + 2 * tig + (q - 2));
            ca4[q] = CA[c]; cb4[q] = CB[c]; cd4[q] = CD[c];
        }
        // 4 rows: (rb2,rb2+2) x (gid, gid+8)
        int rows[4];
        rows[0] = rb2 * 16 + gid;       rows[1] = rows[0] + 8;
        rows[2] = (rb2 + 2) * 16 + gid; rows[3] = rows[2] + 8;
        long ub[4], vb[4];
#pragma unroll
        for (int r = 0; r < 4; r++) {
            ub[r] = (long)ROW[rows[r]] * DDIM;
            vb[r] = (long)TYP[rows[r]] * DDIM;
        }

        for (int chunk = 0; chunk < NCHUNKS; chunk++) {
            const int buf = chunk & 3;
            const int j0  = chunk * 2;

            // prefetch u/v and B before acquiring the buffer
            float2 ur[4], vr[4];
#pragma unroll
            for (int r = 0; r < 4; r++) {
                ur[r] = __ldg((const float2*)(h + ub[r] + j0));
                vr[r] = __ldg((const float2*)(g + vb[r] + j0));
            }
            uint4 breg[8];
            const char* bsrc = (const char*)g_Bh + (long)chunk * 8192;
#pragma unroll
            for (int i = 0; i < 8; i++)
                breg[i] = __ldg((const uint4*)(bsrc + i * 1024 + ptid * 16));

            mbar_wait(smem_base + MB_OFF + 32 + buf * 8, ((chunk >> 2) & 1) ^ 1);

            char* Fb = smc + buf * STAGE_B + F_IN_STG;
            char* Bb = smc + buf * STAGE_B + B_IN_STG;

            // F: fragment-major, one STS.128 per (rb, s)
#pragma unroll
            for (int ri = 0; ri < 2; ri++) {
                const int rb = rb2 + 2 * ri;
                const float2 uA = ur[ri * 2], uB = ur[ri * 2 + 1];
                const float2 vA = vr[ri * 2], vB = vr[ri * 2 + 1];
#pragma unroll
                for (int s = 0; s < 2; s++) {
                    const float ua = s ? uA.y : uA.x, va = s ? vA.y : vA.x;
                    const float ubv = s ? uB.y : uB.x, vbv = s ? vB.y : vB.x;
                    float fA[4], fB[4];
#pragma unroll
                    for (int q = 0; q < 4; q++) {
                        fA[q] = fmaxf(fmaf(ca4[q], ua, fmaf(cb4[q], va, cd4[q])), 0.0f);
                        fB[q] = fmaxf(fmaf(ca4[q], ubv, fmaf(cb4[q], vbv, cd4[q])), 0.0f);
                    }
                    __half2 h0 = __floats2half2_rn(fA[0], fA[1]);
                    __half2 h1 = __floats2half2_rn(fA[2], fA[3]);
                    __half2 h2 = __floats2half2_rn(fB[0], fB[1]);
                    __half2 h3 = __floats2half2_rn(fB[2], fB[3]);
                    uint4 pack;
                    pack.x = *(uint32_t*)&h0; pack.y = *(uint32_t*)&h1;
                    pack.z = *(uint32_t*)&h2; pack.w = *(uint32_t*)&h3;
                    *(uint4*)(Fb + (((s * 4 + rb) * 32) + gid * 4 + tig) * 16) = pack;
                }
            }
            // B: copy prefetched fragments
#pragma unroll
            for (int i = 0; i < 8; i++)
                *(uint4*)(Bb + i * 1024 + ptid * 16) = breg[i];

            mbar_arrive(smem_base + MB_OFF + buf * 8);
        }
    } else {
        // ================= CONSUMER (warps 0-7, 2m x 4n, k16) =================
        const int wid  = tid >> 5;
        const int lane = tid & 31;
        const int gid  = lane >> 2;
        const int tig  = lane & 3;
        const int ebase = (wid & 1) * 32;      // 32-row half
        const int nblk0 = (wid >> 1) * 4;      // 4 n8-blocks

        float acc[2][4][4];
#pragma unroll
        for (int mt = 0; mt < 2; mt++)
#pragma unroll
            for (int nt = 0; nt < 4; nt++)
#pragma unroll
                for (int q = 0; q < 4; q++) acc[mt][nt][q] = 0.0f;

        for (int chunk = 0; chunk < NCHUNKS; chunk++) {
            const int buf = chunk & 3;
            mbar_wait(smem_base + MB_OFF + buf * 8, (chunk >> 2) & 1);
            const char* Fb = smc + buf * STAGE_B + F_IN_STG;
            const char* Bb = smc + buf * STAGE_B + B_IN_STG;
#pragma unroll
            for (int s = 0; s < 2; s++) {
                uint4 va[2];
#pragma unroll
                for (int mt = 0; mt < 2; mt++) {
                    const int rb = (wid & 1) * 2 + mt;
                    va[mt] = *(const uint4*)(Fb + ((s * 4 + rb) * 32 + lane) * 16);
                }
                uint2 vb[4];
#pragma unroll
                for (int nt = 0; nt < 4; nt++)
                    vb[nt] = *(const uint2*)(Bb + ((s * 16 + nblk0 + nt) * 32 + lane) * 8);
#pragma unroll
                for (int nt = 0; nt < 4; nt++) {
#pragma unroll
                    for (int mt = 0; mt < 2; mt++)
                        mma_f16(acc[mt][nt], va[mt].x, va[mt].z, va[mt].y, va[mt].w,
                                vb[nt].x, vb[nt].y);
                }
            }
            mbar_arrive(smem_base + MB_OFF + 32 + buf * 8);
        }

        // ---- epilogue: bn3 + relu + dot(h[col]) ----
        long cbase[4];
#pragma unroll
        for (int rr = 0; rr < 4; rr++) {
            const int e = ebase + (rr >> 1) * 16 + (rr & 1) * 8 + gid;
            cbase[rr] = (long)COL[e] * DDIM;
        }
        float dotp[4] = {0.f, 0.f, 0.f, 0.f};
#pragma unroll
        for (int nt = 0; nt < 4; nt++) {
            const int n = (wid >> 1) * 32 + nt * 8 + 2 * tig;
            const float2 s3 = *(const float2*)&S3[n];
            const float2 q3 = *(const float2*)&Q3[n];
#pragma unroll
            for (int mt = 0; mt < 2; mt++) {
#pragma unroll
                for (int hh = 0; hh < 2; hh++) {
                    const int rr = mt * 2 + hh;
                    float z0 = fmaxf(fmaf(acc[mt][nt][hh * 2 + 0], s3.x, q3.x), 0.0f);
                    float z1 = fmaxf(fmaf(acc[mt][nt][hh * 2 + 1], s3.y, q3.y), 0.0f);
                    const float2 c2 = __ldg((const float2*)(h + cbase[rr] + n));
                    dotp[rr] = fmaf(z0, c2.x, fmaf(z1, c2.y, dotp[rr]));
                }
            }
        }
        float* dsum = (float*)(smc + DS_OFF);
#pragma unroll
        for (int rr = 0; rr < 4; rr++) {
            float s = dotp[rr];
            s += __shfl_xor_sync(0xffffffffu, s, 1, 4);
            s += __shfl_xor_sync(0xffffffffu, s, 2, 4);
            if (tig == 0) {
                const int e = ebase + (rr >> 1) * 16 + (rr & 1) * 8 + gid;
                dsum[(wid >> 1) * TILE_E + e] = s;
            }
        }
    }

    __syncthreads();   // join producers + consumers
    if (tid < TILE_E) {
        const float* ds = (const float*)(smc + DS_OFF);
        out[e0 + tid] = (ds[tid] + ds[TILE_E + tid]) +
                        (ds[2 * TILE_E + tid] + ds[3 * TILE_E + tid]);
    }
}

// ===== launch =====
extern "C" void kernel_launch(void* const* d_in, const int* in_sizes, int n_in,
                              void* d_out, int out_size)
{
    const float* h      = (const float*)d_in[0];
    const float* g      = (const float*)d_in[1];
    const int*   eidx   = (const int*)d_in[2];
    const int*   etype  = (const int*)d_in[3];
    const float* conv_w = (const float*)d_in[4];
    const float* conv_b = (const float*)d_in[5];
    const float* fc_w   = (const float*)d_in[6];
    const float* fc_b   = (const float*)d_in[7];
    const float* bn1g   = (const float*)d_in[8];
    const float* bn1b   = (const float*)d_in[9];
    const float* bn1m   = (const float*)d_in[10];
    const float* bn1v   = (const float*)d_in[11];
    const float* bn3g   = (const float*)d_in[12];
    const float* bn3b   = (const float*)d_in[13];
    const float* bn3m   = (const float*)d_in[14];
    const float* bn3v   = (const float*)d_in[15];
    float* out = (float*)d_out;

    conve_prep<<<256, 256>>>(fc_w);   // 65536 8B fragment units

    cudaFuncSetAttribute(conve_main,
                         cudaFuncAttributeMaxDynamicSharedMemorySize, SMEM_BYTES);
    conve_main<<<E_TOT / TILE_E, NTHREADS, SMEM_BYTES>>>(
        h, g, eidx, etype, conv_w, conv_b, fc_b,
        bn1g, bn1b, bn1m, bn1v, bn3g, bn3b, bn3m, bn3v, out);
}

// round 9
// speedup vs baseline: 7.4153x; 1.1803x over previous
#include <cuda_runtime.h>
#include <cuda_fp16.h>
#include <cstdint>

#define E_TOT    131072
#define DDIM     128
#define KTOT     2048
#define TILE_E   64
#define NTHREADS 256
#define NCHUNKS  64
#define U2STRIDE 66            // half2 units per row (64 + 2 pad -> conflict-free)

// ---- SMEM byte offsets ----
#define U_OFF    0             // 64 * 66 * 4 = 16896
#define V_OFF    16896
#define S3_OFF   33792         // 128 f
#define Q3_OFF   34304
#define CA_OFF   34816         // 16 f
#define CB_OFF   34880
#define CD_OFF   34944
#define ROW_OFF  35008         // 64 i
#define COL_OFF  35264
#define TYP_OFF  35520
#define DS_OFF   35776         // 4 * 64 f = 1024
#define SMEM_BYTES 36864

// fc_w in fp16, fragment-major: [chunk][s][nblk][lane] * 4 halves (8B units)
// lane = gid*4+tig; halves = {B[c=2tig][n], B[2tig+1][n], B[8+2tig][n], B[9+2tig][n]}
// n = nblk*8+gid; j = chunk*2+s; klog = c*128+j
__device__ __half g_Bh[NCHUNKS * 2 * 16 * 32 * 4];

__device__ __forceinline__ void mma_f16(float* c, uint32_t a0, uint32_t a1,
                                        uint32_t a2, uint32_t a3,
                                        uint32_t b0, uint32_t b1) {
    asm volatile(
        "mma.sync.aligned.m16n8k16.row.col.f32.f16.f16.f32 "
        "{%0,%1,%2,%3}, {%4,%5,%6,%7}, {%8,%9}, {%0,%1,%2,%3};"
        : "+f"(c[0]), "+f"(c[1]), "+f"(c[2]), "+f"(c[3])
        : "r"(a0), "r"(a1), "r"(a2), "r"(a3), "r"(b0), "r"(b1));
}
__device__ __forceinline__ uint32_t h2u(__half2 x) { return *(uint32_t*)&x; }

// ===== prep: fragment-major fp16 B from fc_w (identical to R8, proven) =====
extern "C" __global__ void conve_prep(const float* __restrict__ fc_w)
{
    const int idx = blockIdx.x * 256 + threadIdx.x;     // 0..65535 (8B units)
    const int lane  = idx & 31;
    const int nblk  = (idx >> 5) & 15;
    const int s     = (idx >> 9) & 1;
    const int chunk = idx >> 10;
    const int gid = lane >> 2;
    const int tig = lane & 3;
    const int n = nblk * 8 + gid;
    const int j = chunk * 2 + s;

    const int c0 = 2 * tig, c1 = 2 * tig + 1, c2 = 8 + 2 * tig, c3 = 9 + 2 * tig;
    float f0 = fc_w[(long)(c0 * 128 + j) * DDIM + n];
    float f1 = fc_w[(long)(c1 * 128 + j) * DDIM + n];
    float f2 = fc_w[(long)(c2 * 128 + j) * DDIM + n];
    float f3 = fc_w[(long)(c3 * 128 + j) * DDIM + n];
    __half2* dst = (__half2*)(g_Bh + (long)idx * 4);
    dst[0] = __floats2half2_rn(f0, f1);
    dst[1] = __floats2half2_rn(f2, f3);
}

// ===== main: 2 CTAs/SM, 8 uniform warps, zero hot-loop sync =====
extern "C" __global__ void __launch_bounds__(NTHREADS, 2)
conve_main(const float* __restrict__ h, const float* __restrict__ g,
           const int* __restrict__ eidx, const int* __restrict__ etype,
           const float* __restrict__ conv_w, const float* __restrict__ conv_b,
           const float* __restrict__ fc_b,
           const float* __restrict__ bn1g, const float* __restrict__ bn1b,
           const float* __restrict__ bn1m, const float* __restrict__ bn1v,
           const float* __restrict__ bn3g, const float* __restrict__ bn3b,
           const float* __restrict__ bn3m, const float* __restrict__ bn3v,
           float* __restrict__ out)
{
    extern __shared__ char smc[];
    __half2* U2 = (__half2*)(smc + U_OFF);
    __half2* V2 = (__half2*)(smc + V_OFF);
    float* S3 = (float*)(smc + S3_OFF);
    float* Q3 = (float*)(smc + Q3_OFF);
    float* CA = (float*)(smc + CA_OFF);
    float* CB = (float*)(smc + CB_OFF);
    float* CD = (float*)(smc + CD_OFF);
    int* ROW = (int*)(smc + ROW_OFF);
    int* COL = (int*)(smc + COL_OFF);
    int* TYP = (int*)(smc + TYP_OFF);

    const int tid  = threadIdx.x;
    const int wid  = tid >> 5;
    const int lane = tid & 31;
    const int gid  = lane >> 2;
    const int tig  = lane & 3;
    const int e0   = blockIdx.x * TILE_E;

    if (tid < DDIM) {
        float s = bn3g[tid] * rsqrtf(bn3v[tid] + 1e-5f);
        S3[tid] = s;
        Q3[tid] = fc_b[tid] * s + bn3b[tid] - bn3m[tid] * s;
    }
    if (tid < TILE_E) {
        ROW[tid] = eidx[e0 + tid];
        COL[tid] = eidx[E_TOT + e0 + tid];
        TYP[tid] = etype[e0 + tid];
    }
    if (tid < 16) {
        float s1 = bn1g[0] * rsqrtf(bn1v[0] + 1e-5f);
        float b1 = bn1b[0] - bn1m[0] * s1;
        float w0 = conv_w[tid * 2], w1 = conv_w[tid * 2 + 1];
        CA[tid] = w0 * s1;
        CB[tid] = w1 * s1;
        CD[tid] = (w0 + w1) * b1 + conv_b[tid];
    }
    __syncthreads();

    // ---- gather h[row], g[type] -> fp16 SMEM [row][j-pair], once ----
    {
        const int row = tid >> 2;
        const int jq  = tid & 3;            // 32 j-values each
        const float* hp = h + (long)ROW[row] * DDIM + jq * 32;
        const float* gp = g + (long)TYP[row] * DDIM + jq * 32;
#pragma unroll
        for (int i = 0; i < 8; i++) {
            const float4 fu = __ldg((const float4*)(hp + i * 4));
            const float4 fv = __ldg((const float4*)(gp + i * 4));
            __half2 u0 = __floats2half2_rn(fu.x, fu.y);
            __half2 u1 = __floats2half2_rn(fu.z, fu.w);
            __half2 v0 = __floats2half2_rn(fv.x, fv.y);
            __half2 v1 = __floats2half2_rn(fv.z, fv.w);
            const int o = row * U2STRIDE + jq * 16 + i * 2;
            U2[o] = u0; U2[o + 1] = u1;
            V2[o] = v0; V2[o + 1] = v1;
        }
    }
    __syncthreads();

    // ---- per-lane channel-pair coefficients (half2) ----
    __half2 ca2[2], cb2[2], cd2[2];
#pragma unroll
    for (int p = 0; p < 2; p++) {
        const int c = p * 8 + 2 * tig;
        ca2[p] = __floats2half2_rn(CA[c], CA[c + 1]);
        cb2[p] = __floats2half2_rn(CB[c], CB[c + 1]);
        cd2[p] = __floats2half2_rn(CD[c], CD[c + 1]);
    }
    const __half2 zero2 = __floats2half2_rn(0.0f, 0.0f);

    const int ebase = (wid & 1) * 32;
    const int nblk0 = (wid >> 1) * 4;
    const int r0    = ebase + gid;

    float acc[2][4][4];
#pragma unroll
    for (int mt = 0; mt < 2; mt++)
#pragma unroll
        for (int nt = 0; nt < 4; nt++)
#pragma unroll
            for (int q = 0; q < 4; q++) acc[mt][nt][q] = 0.0f;

    // ---- B fragment pointers + prefetch chunk 0 ----
    const uint2* Bp = (const uint2*)g_Bh;
    uint2 vb[2][4], vbn[2][4];
#pragma unroll
    for (int s = 0; s < 2; s++)
#pragma unroll
        for (int nt = 0; nt < 4; nt++)
            vb[s][nt] = __ldg(Bp + s * 512 + (nblk0 + nt) * 32 + lane);

    for (int chunk = 0; chunk < NCHUNKS; chunk++) {
        // prefetch next chunk's B into registers (hides L2 latency)
        if (chunk < NCHUNKS - 1) {
            const uint2* bn = Bp + (chunk + 1) * 1024;
#pragma unroll
            for (int s = 0; s < 2; s++)
#pragma unroll
                for (int nt = 0; nt < 4; nt++)
                    vbn[s][nt] = __ldg(bn + s * 512 + (nblk0 + nt) * 32 + lane);
        }

        // load u/v half2 (j0, j0+1) for this lane's 4 rows
        __half2 u2[4], v2[4];
#pragma unroll
        for (int q = 0; q < 4; q++) {
            const int o = (r0 + q * 8) * U2STRIDE + chunk;
            u2[q] = U2[o];
            v2[q] = V2[o];
        }

#pragma unroll
        for (int s = 0; s < 2; s++) {
            // feat fragments: rows r0, r0+8, r0+16, r0+24; channel pairs lo/hi
            uint32_t flo[4], fhi[4];
#pragma unroll
            for (int q = 0; q < 4; q++) {
                const __half2 uu = s ? __high2half2(u2[q]) : __low2half2(u2[q]);
                const __half2 vv = s ? __high2half2(v2[q]) : __low2half2(v2[q]);
                __half2 t0 = __hfma2(cb2[0], vv, cd2[0]);
                __half2 t1 = __hfma2(cb2[1], vv, cd2[1]);
                t0 = __hmax2(__hfma2(ca2[0], uu, t0), zero2);
                t1 = __hmax2(__hfma2(ca2[1], uu, t1), zero2);
                flo[q] = h2u(t0);
                fhi[q] = h2u(t1);
            }
#pragma unroll
            for (int nt = 0; nt < 4; nt++) {
#pragma unroll
                for (int mt = 0; mt < 2; mt++)
                    mma_f16(acc[mt][nt],
                            flo[2 * mt], flo[2 * mt + 1],
                            fhi[2 * mt], fhi[2 * mt + 1],
                            vb[s][nt].x, vb[s][nt].y);
            }
        }
#pragma unroll
        for (int s = 0; s < 2; s++)
#pragma unroll
            for (int nt = 0; nt < 4; nt++)
                vb[s][nt] = vbn[s][nt];
    }

    // ---- epilogue: bn3 + relu + dot(h[col]) ----
    long cbase[4];
#pragma unroll
    for (int rr = 0; rr < 4; rr++) {
        const int e = ebase + (rr >> 1) * 16 + (rr & 1) * 8 + gid;
        cbase[rr] = (long)COL[e] * DDIM;
    }
    float dotp[4] = {0.f, 0.f, 0.f, 0.f};
#pragma unroll
    for (int nt = 0; nt < 4; nt++) {
        const int n = (wid >> 1) * 32 + nt * 8 + 2 * tig;
        const float2 s3 = *(const float2*)&S3[n];
        const float2 q3 = *(const float2*)&Q3[n];
#pragma unroll
        for (int mt = 0; mt < 2; mt++) {
#pragma unroll
            for (int hh = 0; hh < 2; hh++) {
                const int rr = mt * 2 + hh;
                float z0 = fmaxf(fmaf(acc[mt][nt][hh * 2 + 0], s3.x, q3.x), 0.0f);
                float z1 = fmaxf(fmaf(acc[mt][nt][hh * 2 + 1], s3.y, q3.y), 0.0f);
                const float2 c2 = __ldg((const float2*)(h + cbase[rr] + n));
                dotp[rr] = fmaf(z0, c2.x, fmaf(z1, c2.y, dotp[rr]));
            }
        }
    }
    float* dsum = (float*)(smc + DS_OFF);
#pragma unroll
    for (int rr = 0; rr < 4; rr++) {
        float s = dotp[rr];
        s += __shfl_xor_sync(0xffffffffu, s, 1, 4);
        s += __shfl_xor_sync(0xffffffffu, s, 2, 4);
        if (tig == 0) {
            const int e = ebase + (rr >> 1) * 16 + (rr & 1) * 8 + gid;
            dsum[(wid >> 1) * TILE_E + e] = s;
        }
    }
    __syncthreads();
    if (tid < TILE_E) {
        const float* ds = (const float*)(smc + DS_OFF);
        out[e0 + tid] = (ds[tid] + ds[TILE_E + tid]) +
                        (ds[2 * TILE_E + tid] + ds[3 * TILE_E + tid]);
    }
}

// ===== launch =====
extern "C" void kernel_launch(void* const* d_in, const int* in_sizes, int n_in,
                              void* d_out, int out_size)
{
    const float* h      = (const float*)d_in[0];
    const float* g      = (const float*)d_in[1];
    const int*   eidx   = (const int*)d_in[2];
    const int*   etype  = (const int*)d_in[3];
    const float* conv_w = (const float*)d_in[4];
    const float* conv_b = (const float*)d_in[5];
    const float* fc_w   = (const float*)d_in[6];
    const float* fc_b   = (const float*)d_in[7];
    const float* bn1g   = (const float*)d_in[8];
    const float* bn1b   = (const float*)d_in[9];
    const float* bn1m   = (const float*)d_in[10];
    const float* bn1v   = (const float*)d_in[11];
    const float* bn3g   = (const float*)d_in[12];
    const float* bn3b   = (const float*)d_in[13];
    const float* bn3m   = (const float*)d_in[14];
    const float* bn3v   = (const float*)d_in[15];
    float* out = (float*)d_out;

    conve_prep<<<256, 256>>>(fc_w);

    cudaFuncSetAttribute(conve_main,
                         cudaFuncAttributeMaxDynamicSharedMemorySize, SMEM_BYTES);
    conve_main<<<E_TOT / TILE_E, NTHREADS, SMEM_BYTES>>>(
        h, g, eidx, etype, conv_w, conv_b, fc_b,
        bn1g, bn1b, bn1m, bn1v, bn3g, bn3b, bn3m, bn3v, out);
}